// round 1
// baseline (speedup 1.0000x reference)
#include <cuda_runtime.h>
#include <math.h>

#define T_LEN 2048
#define DIM   768
#define NH    12
#define HD    64

// ---------------- scratch (no allocation allowed) ----------------
__device__ float g_q[T_LEN * DIM];
__device__ float g_k[T_LEN * DIM];
__device__ float g_v[T_LEN * DIM];
__device__ float g_y[T_LEN * DIM];

// ---------------- GEMM: C = A @ B^T (optionally blended) ----------------
// A [M,K] row-major, B [N,K] row-major, C [M,N] row-major.
// blockIdx.z selects (W,C) among 3; z==2 with addsrc != nullptr does
// C = (1-lamb)*A@B^T + lamb*addsrc.
#define GBM 128
#define GBN 128
#define GBK 8

__global__ __launch_bounds__(256)
void gemm_nt(const float* __restrict__ A,
             const float* __restrict__ W0, const float* __restrict__ W1,
             const float* __restrict__ W2,
             float* __restrict__ C0, float* __restrict__ C1, float* __restrict__ C2,
             const float* __restrict__ addsrc, const float* __restrict__ lamb_ptr,
             int M, int N, int K)
{
    const int z = blockIdx.z;
    const float* B = (z == 0) ? W0 : (z == 1) ? W1 : W2;
    float*       C = (z == 0) ? C0 : (z == 1) ? C1 : C2;

    __shared__ float As[GBK][GBM + 4];
    __shared__ float Bs[GBK][GBN + 4];

    const int tid = threadIdx.x;
    const int bm = blockIdx.y * GBM;
    const int bn = blockIdx.x * GBN;
    const int tx = tid & 15;       // 16 thread cols
    const int ty = tid >> 4;       // 16 thread rows
    const int lrow = tid >> 1;     // 0..127
    const int lk   = (tid & 1) * 4;

    const float* Ag = A + (size_t)(bm + lrow) * K + lk;
    const float* Bg = B + (size_t)(bn + lrow) * K + lk;

    float4 a4 = *(const float4*)Ag;
    float4 b4 = *(const float4*)Bg;

    float acc[8][8];
#pragma unroll
    for (int i = 0; i < 8; i++)
#pragma unroll
        for (int j = 0; j < 8; j++) acc[i][j] = 0.f;

    const int nt = K / GBK;
    for (int kt = 0; kt < nt; kt++) {
        As[lk + 0][lrow] = a4.x; As[lk + 1][lrow] = a4.y;
        As[lk + 2][lrow] = a4.z; As[lk + 3][lrow] = a4.w;
        Bs[lk + 0][lrow] = b4.x; Bs[lk + 1][lrow] = b4.y;
        Bs[lk + 2][lrow] = b4.z; Bs[lk + 3][lrow] = b4.w;
        __syncthreads();

        if (kt + 1 < nt) {
            a4 = *(const float4*)(Ag + (size_t)(kt + 1) * GBK);
            b4 = *(const float4*)(Bg + (size_t)(kt + 1) * GBK);
        }

#pragma unroll
        for (int kk = 0; kk < GBK; kk++) {
            float4 aa0 = *(const float4*)&As[kk][ty * 8];
            float4 aa1 = *(const float4*)&As[kk][ty * 8 + 4];
            float4 bb0 = *(const float4*)&Bs[kk][tx * 8];
            float4 bb1 = *(const float4*)&Bs[kk][tx * 8 + 4];
            float av[8] = {aa0.x, aa0.y, aa0.z, aa0.w, aa1.x, aa1.y, aa1.z, aa1.w};
            float bv[8] = {bb0.x, bb0.y, bb0.z, bb0.w, bb1.x, bb1.y, bb1.z, bb1.w};
#pragma unroll
            for (int i = 0; i < 8; i++)
#pragma unroll
                for (int j = 0; j < 8; j++)
                    acc[i][j] += av[i] * bv[j];
        }
        __syncthreads();
    }

    const bool blend = (z == 2) && (addsrc != nullptr);
    const float lb = blend ? *lamb_ptr : 0.f;
    const float om = 1.f - lb;

#pragma unroll
    for (int i = 0; i < 8; i++) {
        const int r = bm + ty * 8 + i;
        float* Crow = C + (size_t)r * N + bn + tx * 8;
        const float* Srow = addsrc ? (addsrc + (size_t)r * N + bn + tx * 8) : nullptr;
#pragma unroll
        for (int j = 0; j < 8; j += 4) {
            float4 o;
            o.x = acc[i][j + 0]; o.y = acc[i][j + 1];
            o.z = acc[i][j + 2]; o.w = acc[i][j + 3];
            if (blend) {
                o.x = om * o.x + lb * Srow[j + 0];
                o.y = om * o.y + lb * Srow[j + 1];
                o.z = om * o.z + lb * Srow[j + 2];
                o.w = om * o.w + lb * Srow[j + 3];
            }
            *(float4*)(Crow + j) = o;
        }
    }
}

// ---------------- RMSNorm + RoPE (in place on g_q / g_k) ----------------
// One warp handles one (tensor, token, head): 64 values, lane j owns the
// rotary pair (x[j], x[j+32]).
__global__ __launch_bounds__(256)
void norm_rope_kernel()
{
    const int wid  = blockIdx.x * 8 + (threadIdx.x >> 5);
    const int lane = threadIdx.x & 31;
    const int tsel = wid / (T_LEN * NH);
    const int rem  = wid % (T_LEN * NH);
    const int t = rem / NH;
    const int h = rem % NH;

    float* base = (tsel ? g_k : g_q) + (size_t)t * DIM + h * HD;

    float x1 = base[lane];
    float x2 = base[lane + 32];

    float ss = x1 * x1 + x2 * x2;
#pragma unroll
    for (int o = 16; o; o >>= 1) ss += __shfl_xor_sync(0xffffffffu, ss, o);
    const float ms = ss * (1.f / 64.f);
    const float rn = rsqrtf(ms + 1.1920929e-07f);   // eps = finfo(f32).eps
    x1 *= rn; x2 *= rn;

    // inv_freq = 10000^{-lane/32}, angle = t * inv_freq (all fp32, like ref)
    const float inv = expf(-(float)lane * 0.28782313662425572f); // ln(1e4)/32
    const float ang = (float)t * inv;
    const float c = cosf(ang);
    const float s = sinf(ang);

    base[lane]      =  x1 * c + x2 * s;
    base[lane + 32] = -x1 * s + x2 * c;
}

// ---------------- causal flash attention (fp32) ----------------
// CTA = (query block of 64, head). 8 warps * 8 rows. Online softmax.
// smem: q[64][64], kT[64][65], v[64][64], p[8 warps][8][64]
#define ATTN_SMEM_FLOATS (4096 + 64 * 65 + 4096 + 4096)
#define ATTN_SMEM_BYTES  (ATTN_SMEM_FLOATS * 4)

__global__ __launch_bounds__(256)
void attn_kernel(const float* __restrict__ q, const float* __restrict__ k,
                 const float* __restrict__ v, float* __restrict__ y)
{
    extern __shared__ float sm[];
    float* q_s  = sm;                        // [64][64]
    float* kT_s = sm + 4096;                 // [64][65]  kT_s[d][key]
    float* v_s  = kT_s + 64 * 65;            // [64][64]
    float* p_s  = v_s + 4096;                // [8][8][64]

    const int h    = blockIdx.y;
    const int qb   = blockIdx.x;
    const int tid  = threadIdx.x;
    const int w    = tid >> 5;
    const int lane = tid & 31;
    const int q0   = qb * 64;
    const int rbase = w * 8;

    // load q tile, pre-scaled by 1/sqrt(64)
    {
        const int row = tid >> 2, part = tid & 3;
        const float4* src = (const float4*)(q + (size_t)(q0 + row) * DIM + h * HD + part * 16);
        float4* dst = (float4*)(q_s + row * 64 + part * 16);
#pragma unroll
        for (int i = 0; i < 4; i++) {
            float4 tq = src[i];
            tq.x *= 0.125f; tq.y *= 0.125f; tq.z *= 0.125f; tq.w *= 0.125f;
            dst[i] = tq;
        }
    }

    float m[8], l[8], acc[8][2];
#pragma unroll
    for (int r = 0; r < 8; r++) {
        m[r] = -INFINITY; l[r] = 0.f; acc[r][0] = 0.f; acc[r][1] = 0.f;
    }

    for (int kb = 0; kb <= qb; kb++) {
        __syncthreads();   // protects q_s on iter 0, kT/v reuse afterwards
        {
            const int key = tid >> 2, part = tid & 3;
            const float4* ks = (const float4*)(k + (size_t)(kb * 64 + key) * DIM + h * HD + part * 16);
            const float4* vs = (const float4*)(v + (size_t)(kb * 64 + key) * DIM + h * HD + part * 16);
            float4* vd = (float4*)(v_s + key * 64 + part * 16);
#pragma unroll
            for (int i = 0; i < 4; i++) {
                float4 kv = ks[i];
                const int d = part * 16 + i * 4;
                kT_s[(d + 0) * 65 + key] = kv.x;
                kT_s[(d + 1) * 65 + key] = kv.y;
                kT_s[(d + 2) * 65 + key] = kv.z;
                kT_s[(d + 3) * 65 + key] = kv.w;
                vd[i] = vs[i];
            }
        }
        __syncthreads();

        // scores: s[r][j], key = j*32 + lane
        float s[8][2];
#pragma unroll
        for (int r = 0; r < 8; r++) { s[r][0] = 0.f; s[r][1] = 0.f; }

#pragma unroll 4
        for (int d4 = 0; d4 < 16; d4++) {
            const int d = d4 * 4;
            float k0[4], k1[4];
#pragma unroll
            for (int dd = 0; dd < 4; dd++) {
                k0[dd] = kT_s[(d + dd) * 65 + lane];
                k1[dd] = kT_s[(d + dd) * 65 + 32 + lane];
            }
#pragma unroll
            for (int r = 0; r < 8; r++) {
                float4 qv = *(const float4*)(q_s + (rbase + r) * 64 + d);
                s[r][0] += qv.x * k0[0] + qv.y * k0[1] + qv.z * k0[2] + qv.w * k0[3];
                s[r][1] += qv.x * k1[0] + qv.y * k1[1] + qv.z * k1[2] + qv.w * k1[3];
            }
        }

        if (kb == qb) {
#pragma unroll
            for (int r = 0; r < 8; r++) {
                const int qrow = rbase + r;
                if (lane > qrow)      s[r][0] = -INFINITY;
                if (lane + 32 > qrow) s[r][1] = -INFINITY;
            }
        }

        // online softmax + stage P in smem
#pragma unroll
        for (int r = 0; r < 8; r++) {
            float mx = fmaxf(s[r][0], s[r][1]);
#pragma unroll
            for (int o = 16; o; o >>= 1) mx = fmaxf(mx, __shfl_xor_sync(0xffffffffu, mx, o));
            const float mn = fmaxf(m[r], mx);
            const float p0 = __expf(s[r][0] - mn);
            const float p1 = __expf(s[r][1] - mn);
            float ps = p0 + p1;
#pragma unroll
            for (int o = 16; o; o >>= 1) ps += __shfl_xor_sync(0xffffffffu, ps, o);
            const float alpha = __expf(m[r] - mn);
            l[r] = l[r] * alpha + ps;
            acc[r][0] *= alpha; acc[r][1] *= alpha;
            m[r] = mn;
            p_s[(w * 8 + r) * 64 + lane]      = p0;
            p_s[(w * 8 + r) * 64 + 32 + lane] = p1;
        }
        __syncwarp();

        // PV: out[r][c], c = j*32 + lane
#pragma unroll 4
        for (int k4 = 0; k4 < 16; k4++) {
            const int kk = k4 * 4;
            float v0[4], v1[4];
#pragma unroll
            for (int i = 0; i < 4; i++) {
                v0[i] = v_s[(kk + i) * 64 + lane];
                v1[i] = v_s[(kk + i) * 64 + 32 + lane];
            }
#pragma unroll
            for (int r = 0; r < 8; r++) {
                float4 p4 = *(const float4*)(p_s + (w * 8 + r) * 64 + kk);
                acc[r][0] += p4.x * v0[0] + p4.y * v0[1] + p4.z * v0[2] + p4.w * v0[3];
                acc[r][1] += p4.x * v1[0] + p4.y * v1[1] + p4.z * v1[2] + p4.w * v1[3];
            }
        }
    }

#pragma unroll
    for (int r = 0; r < 8; r++) {
        const float inv = 1.f / l[r];
        const int t = q0 + rbase + r;
        y[(size_t)t * DIM + h * HD + lane]      = acc[r][0] * inv;
        y[(size_t)t * DIM + h * HD + 32 + lane] = acc[r][1] * inv;
    }
}

// ---------------- launch ----------------
extern "C" void kernel_launch(void* const* d_in, const int* in_sizes, int n_in,
                              void* d_out, int out_size)
{
    const float* x    = (const float*)d_in[0];
    const float* vi   = (const float*)d_in[1];
    const float* Wq   = (const float*)d_in[2];
    const float* Wk   = (const float*)d_in[3];
    const float* Wv   = (const float*)d_in[4];
    const float* Wp   = (const float*)d_in[5];
    const float* lamb = (const float*)d_in[6];
    float* out = (float*)d_out;

    float *q, *k, *v, *y;
    cudaGetSymbolAddress((void**)&q, g_q);
    cudaGetSymbolAddress((void**)&k, g_k);
    cudaGetSymbolAddress((void**)&v, g_v);
    cudaGetSymbolAddress((void**)&y, g_y);

    cudaFuncSetAttribute(attn_kernel, cudaFuncAttributeMaxDynamicSharedMemorySize,
                         ATTN_SMEM_BYTES);

    // fused QKV GEMM (z selects Wq/Wk/Wv; z==2 blends with vi)
    dim3 gqkv(DIM / GBN, T_LEN / GBM, 3);
    gemm_nt<<<gqkv, 256>>>(x, Wq, Wk, Wv, q, k, v, vi, lamb, T_LEN, DIM, DIM);

    // RMSNorm + RoPE on q and k (in place)
    norm_rope_kernel<<<(2 * T_LEN * NH) / 8, 256>>>();

    // causal attention
    dim3 gattn(T_LEN / 64, NH);
    attn_kernel<<<gattn, 256, ATTN_SMEM_BYTES>>>(q, k, v, y);

    // output projection
    dim3 gproj(DIM / GBN, T_LEN / GBM, 1);
    gemm_nt<<<gproj, 256>>>(y, Wp, Wp, Wp, out, out, out, nullptr, nullptr,
                            T_LEN, DIM, DIM);
}

// round 2
// speedup vs baseline: 1.4148x; 1.4148x over previous
#include <cuda_runtime.h>
#include <math.h>

#define T_LEN 2048
#define DIM   768
#define NH    12
#define HD    64

// ---------------- scratch (no allocation allowed) ----------------
__device__ float g_q[T_LEN * DIM];
__device__ float g_k[T_LEN * DIM];
__device__ float g_v[T_LEN * DIM];
__device__ float g_y[T_LEN * DIM];

// =====================================================================
// tf32 tensor-core GEMM:  C = A @ B^T   (A [M,K], B [N,K], C [M,N])
// CTA tile 128x128, 8 warps (2x4), warp tile 64x32 = 4x4 m16n8k8 tiles.
// K-chunk 32, 2-stage cp.async double buffer.
// blockIdx.z selects (W,C); z==2 with addsrc: C = (1-lamb)*A@B^T + lamb*addsrc
// =====================================================================
#define KC      32
#define GSTRIDE 36          // smem row stride in floats (conflict-free: 36 % 32 == 4)
#define STAGE_FLOATS (2 * 128 * GSTRIDE)       // A tile + B tile per stage
#define GEMM_SMEM_BYTES (2 * STAGE_FLOATS * 4) // 73728

__device__ __forceinline__ unsigned f2tf32(float f) {
    unsigned u;
    asm("cvt.rna.tf32.f32 %0, %1;" : "=r"(u) : "f"(f));
    return u;
}

__device__ __forceinline__ void mma8(float* c, const unsigned* a, const unsigned* b) {
    asm volatile(
        "mma.sync.aligned.m16n8k8.row.col.f32.tf32.tf32.f32 "
        "{%0,%1,%2,%3}, {%4,%5,%6,%7}, {%8,%9}, {%0,%1,%2,%3};\n"
        : "+f"(c[0]), "+f"(c[1]), "+f"(c[2]), "+f"(c[3])
        : "r"(a[0]), "r"(a[1]), "r"(a[2]), "r"(a[3]), "r"(b[0]), "r"(b[1]));
}

__device__ __forceinline__ void cp16(void* smem_dst, const void* gsrc) {
    unsigned d = (unsigned)__cvta_generic_to_shared(smem_dst);
    asm volatile("cp.async.ca.shared.global [%0], [%1], 16;\n" :: "r"(d), "l"(gsrc));
}

__device__ __forceinline__ void load_stage(float* As, float* Bs,
                                           const float* A, const float* B,
                                           int bm, int bn, int k0, int K, int tid)
{
    const int row = tid >> 3;          // 0..31
    const int col = (tid & 7) * 4;     // 0..28
#pragma unroll
    for (int p = 0; p < 4; p++) {
        const int r = row + p * 32;
        cp16(&As[r * GSTRIDE + col], A + (size_t)(bm + r) * K + k0 + col);
        cp16(&Bs[r * GSTRIDE + col], B + (size_t)(bn + r) * K + k0 + col);
    }
}

__global__ __launch_bounds__(256)
void gemm_tf32(const float* __restrict__ A,
               const float* __restrict__ W0, const float* __restrict__ W1,
               const float* __restrict__ W2,
               float* __restrict__ C0, float* __restrict__ C1, float* __restrict__ C2,
               const float* __restrict__ addsrc, const float* __restrict__ lamb_ptr,
               int M, int N, int K)
{
    extern __shared__ float sm[];

    const int z = blockIdx.z;
    const float* B = (z == 0) ? W0 : (z == 1) ? W1 : W2;
    float*       C = (z == 0) ? C0 : (z == 1) ? C1 : C2;

    const int tid  = threadIdx.x;
    const int lane = tid & 31;
    const int warp = tid >> 5;
    const int wm   = warp >> 2;        // 0..1
    const int wn   = warp & 3;         // 0..3
    const int bm   = blockIdx.y * 128;
    const int bn   = blockIdx.x * 128;
    const int gr   = lane >> 2;        // group row 0..7
    const int tig  = lane & 3;         // thread in group

    float acc[4][4][4];
#pragma unroll
    for (int mi = 0; mi < 4; mi++)
#pragma unroll
        for (int ni = 0; ni < 4; ni++)
#pragma unroll
            for (int r = 0; r < 4; r++) acc[mi][ni][r] = 0.f;

    const int nt = K / KC;             // 24

    load_stage(sm, sm + 128 * GSTRIDE, A, B, bm, bn, 0, K, tid);
    asm volatile("cp.async.commit_group;\n");

    for (int t = 0; t < nt; t++) {
        if (t + 1 < nt) {
            float* dst = sm + ((t + 1) & 1) * STAGE_FLOATS;
            load_stage(dst, dst + 128 * GSTRIDE, A, B, bm, bn, (t + 1) * KC, K, tid);
            asm volatile("cp.async.commit_group;\n");
            asm volatile("cp.async.wait_group 1;\n");
        } else {
            asm volatile("cp.async.wait_group 0;\n");
        }
        __syncthreads();

        const float* As = sm + (t & 1) * STAGE_FLOATS;
        const float* Bs = As + 128 * GSTRIDE;

#pragma unroll
        for (int ks = 0; ks < 4; ks++) {
            const int kk = ks * 8;
            unsigned a[4][4], b[4][2];
#pragma unroll
            for (int mi = 0; mi < 4; mi++) {
                const int r = wm * 64 + mi * 16 + gr;
                const int c = kk + tig;
                a[mi][0] = f2tf32(As[r * GSTRIDE + c]);
                a[mi][1] = f2tf32(As[(r + 8) * GSTRIDE + c]);
                a[mi][2] = f2tf32(As[r * GSTRIDE + c + 4]);
                a[mi][3] = f2tf32(As[(r + 8) * GSTRIDE + c + 4]);
            }
#pragma unroll
            for (int ni = 0; ni < 4; ni++) {
                const int n = wn * 32 + ni * 8 + gr;
                b[ni][0] = f2tf32(Bs[n * GSTRIDE + kk + tig]);
                b[ni][1] = f2tf32(Bs[n * GSTRIDE + kk + 4 + tig]);
            }
#pragma unroll
            for (int mi = 0; mi < 4; mi++)
#pragma unroll
                for (int ni = 0; ni < 4; ni++)
                    mma8(acc[mi][ni], a[mi], b[ni]);
        }
        __syncthreads();
    }

    const bool blend = (z == 2) && (addsrc != nullptr);
    const float lb = blend ? *lamb_ptr : 0.f;
    const float om = 1.f - lb;

#pragma unroll
    for (int mi = 0; mi < 4; mi++) {
#pragma unroll
        for (int ni = 0; ni < 4; ni++) {
            const int r0 = bm + wm * 64 + mi * 16 + gr;
            const int c0 = bn + wn * 32 + ni * 8 + tig * 2;
            float2 v0 = make_float2(acc[mi][ni][0], acc[mi][ni][1]);
            float2 v1 = make_float2(acc[mi][ni][2], acc[mi][ni][3]);
            if (blend) {
                const float* s0 = addsrc + (size_t)r0 * N + c0;
                const float* s1 = addsrc + (size_t)(r0 + 8) * N + c0;
                v0.x = om * v0.x + lb * s0[0];
                v0.y = om * v0.y + lb * s0[1];
                v1.x = om * v1.x + lb * s1[0];
                v1.y = om * v1.y + lb * s1[1];
            }
            *(float2*)(C + (size_t)r0 * N + c0)       = v0;
            *(float2*)(C + (size_t)(r0 + 8) * N + c0) = v1;
        }
    }
}

// ---------------- RMSNorm + RoPE (in place on g_q / g_k) ----------------
__global__ __launch_bounds__(256)
void norm_rope_kernel()
{
    const int wid  = blockIdx.x * 8 + (threadIdx.x >> 5);
    const int lane = threadIdx.x & 31;
    const int tsel = wid / (T_LEN * NH);
    const int rem  = wid % (T_LEN * NH);
    const int t = rem / NH;
    const int h = rem % NH;

    float* base = (tsel ? g_k : g_q) + (size_t)t * DIM + h * HD;

    float x1 = base[lane];
    float x2 = base[lane + 32];

    float ss = x1 * x1 + x2 * x2;
#pragma unroll
    for (int o = 16; o; o >>= 1) ss += __shfl_xor_sync(0xffffffffu, ss, o);
    const float ms = ss * (1.f / 64.f);
    const float rn = rsqrtf(ms + 1.1920929e-07f);
    x1 *= rn; x2 *= rn;

    const float inv = expf(-(float)lane * 0.28782313662425572f); // ln(1e4)/32
    const float ang = (float)t * inv;
    const float c = cosf(ang);
    const float s = sinf(ang);

    base[lane]      =  x1 * c + x2 * s;
    base[lane + 32] = -x1 * s + x2 * c;
}

// ---------------- causal flash attention (fp32) ----------------
#define ATTN_SMEM_FLOATS (4096 + 64 * 65 + 4096 + 4096)
#define ATTN_SMEM_BYTES  (ATTN_SMEM_FLOATS * 4)

__global__ __launch_bounds__(256)
void attn_kernel(const float* __restrict__ q, const float* __restrict__ k,
                 const float* __restrict__ v, float* __restrict__ y)
{
    extern __shared__ float sm[];
    float* q_s  = sm;
    float* kT_s = sm + 4096;
    float* v_s  = kT_s + 64 * 65;
    float* p_s  = v_s + 4096;

    const int h    = blockIdx.y;
    const int qb   = blockIdx.x;
    const int tid  = threadIdx.x;
    const int w    = tid >> 5;
    const int lane = tid & 31;
    const int q0   = qb * 64;
    const int rbase = w * 8;

    {
        const int row = tid >> 2, part = tid & 3;
        const float4* src = (const float4*)(q + (size_t)(q0 + row) * DIM + h * HD + part * 16);
        float4* dst = (float4*)(q_s + row * 64 + part * 16);
#pragma unroll
        for (int i = 0; i < 4; i++) {
            float4 tq = src[i];
            tq.x *= 0.125f; tq.y *= 0.125f; tq.z *= 0.125f; tq.w *= 0.125f;
            dst[i] = tq;
        }
    }

    float m[8], l[8], acc[8][2];
#pragma unroll
    for (int r = 0; r < 8; r++) {
        m[r] = -INFINITY; l[r] = 0.f; acc[r][0] = 0.f; acc[r][1] = 0.f;
    }

    for (int kb = 0; kb <= qb; kb++) {
        __syncthreads();
        {
            const int key = tid >> 2, part = tid & 3;
            const float4* ks = (const float4*)(k + (size_t)(kb * 64 + key) * DIM + h * HD + part * 16);
            const float4* vs = (const float4*)(v + (size_t)(kb * 64 + key) * DIM + h * HD + part * 16);
            float4* vd = (float4*)(v_s + key * 64 + part * 16);
#pragma unroll
            for (int i = 0; i < 4; i++) {
                float4 kv = ks[i];
                const int d = part * 16 + i * 4;
                kT_s[(d + 0) * 65 + key] = kv.x;
                kT_s[(d + 1) * 65 + key] = kv.y;
                kT_s[(d + 2) * 65 + key] = kv.z;
                kT_s[(d + 3) * 65 + key] = kv.w;
                vd[i] = vs[i];
            }
        }
        __syncthreads();

        float s[8][2];
#pragma unroll
        for (int r = 0; r < 8; r++) { s[r][0] = 0.f; s[r][1] = 0.f; }

#pragma unroll 4
        for (int d4 = 0; d4 < 16; d4++) {
            const int d = d4 * 4;
            float k0[4], k1[4];
#pragma unroll
            for (int dd = 0; dd < 4; dd++) {
                k0[dd] = kT_s[(d + dd) * 65 + lane];
                k1[dd] = kT_s[(d + dd) * 65 + 32 + lane];
            }
#pragma unroll
            for (int r = 0; r < 8; r++) {
                float4 qv = *(const float4*)(q_s + (rbase + r) * 64 + d);
                s[r][0] += qv.x * k0[0] + qv.y * k0[1] + qv.z * k0[2] + qv.w * k0[3];
                s[r][1] += qv.x * k1[0] + qv.y * k1[1] + qv.z * k1[2] + qv.w * k1[3];
            }
        }

        if (kb == qb) {
#pragma unroll
            for (int r = 0; r < 8; r++) {
                const int qrow = rbase + r;
                if (lane > qrow)      s[r][0] = -INFINITY;
                if (lane + 32 > qrow) s[r][1] = -INFINITY;
            }
        }

#pragma unroll
        for (int r = 0; r < 8; r++) {
            float mx = fmaxf(s[r][0], s[r][1]);
#pragma unroll
            for (int o = 16; o; o >>= 1) mx = fmaxf(mx, __shfl_xor_sync(0xffffffffu, mx, o));
            const float mn = fmaxf(m[r], mx);
            const float p0 = __expf(s[r][0] - mn);
            const float p1 = __expf(s[r][1] - mn);
            float ps = p0 + p1;
#pragma unroll
            for (int o = 16; o; o >>= 1) ps += __shfl_xor_sync(0xffffffffu, ps, o);
            const float alpha = __expf(m[r] - mn);
            l[r] = l[r] * alpha + ps;
            acc[r][0] *= alpha; acc[r][1] *= alpha;
            m[r] = mn;
            p_s[(w * 8 + r) * 64 + lane]      = p0;
            p_s[(w * 8 + r) * 64 + 32 + lane] = p1;
        }
        __syncwarp();

#pragma unroll 4
        for (int k4 = 0; k4 < 16; k4++) {
            const int kk = k4 * 4;
            float v0[4], v1[4];
#pragma unroll
            for (int i = 0; i < 4; i++) {
                v0[i] = v_s[(kk + i) * 64 + lane];
                v1[i] = v_s[(kk + i) * 64 + 32 + lane];
            }
#pragma unroll
            for (int r = 0; r < 8; r++) {
                float4 p4 = *(const float4*)(p_s + (w * 8 + r) * 64 + kk);
                acc[r][0] += p4.x * v0[0] + p4.y * v0[1] + p4.z * v0[2] + p4.w * v0[3];
                acc[r][1] += p4.x * v1[0] + p4.y * v1[1] + p4.z * v1[2] + p4.w * v1[3];
            }
        }
    }

#pragma unroll
    for (int r = 0; r < 8; r++) {
        const float inv = 1.f / l[r];
        const int t = q0 + rbase + r;
        y[(size_t)t * DIM + h * HD + lane]      = acc[r][0] * inv;
        y[(size_t)t * DIM + h * HD + 32 + lane] = acc[r][1] * inv;
    }
}

// ---------------- launch ----------------
extern "C" void kernel_launch(void* const* d_in, const int* in_sizes, int n_in,
                              void* d_out, int out_size)
{
    const float* x    = (const float*)d_in[0];
    const float* vi   = (const float*)d_in[1];
    const float* Wq   = (const float*)d_in[2];
    const float* Wk   = (const float*)d_in[3];
    const float* Wv   = (const float*)d_in[4];
    const float* Wp   = (const float*)d_in[5];
    const float* lamb = (const float*)d_in[6];
    float* out = (float*)d_out;

    float *q, *k, *v, *y;
    cudaGetSymbolAddress((void**)&q, g_q);
    cudaGetSymbolAddress((void**)&k, g_k);
    cudaGetSymbolAddress((void**)&v, g_v);
    cudaGetSymbolAddress((void**)&y, g_y);

    cudaFuncSetAttribute(attn_kernel, cudaFuncAttributeMaxDynamicSharedMemorySize,
                         ATTN_SMEM_BYTES);
    cudaFuncSetAttribute(gemm_tf32, cudaFuncAttributeMaxDynamicSharedMemorySize,
                         GEMM_SMEM_BYTES);

    // fused QKV GEMM (z selects Wq/Wk/Wv; z==2 blends with vi)
    dim3 gqkv(DIM / 128, T_LEN / 128, 3);
    gemm_tf32<<<gqkv, 256, GEMM_SMEM_BYTES>>>(x, Wq, Wk, Wv, q, k, v, vi, lamb,
                                              T_LEN, DIM, DIM);

    // RMSNorm + RoPE on q and k (in place)
    norm_rope_kernel<<<(2 * T_LEN * NH) / 8, 256>>>();

    // causal attention
    dim3 gattn(T_LEN / 64, NH);
    attn_kernel<<<gattn, 256, ATTN_SMEM_BYTES>>>(q, k, v, y);

    // output projection
    dim3 gproj(DIM / 128, T_LEN / 128, 1);
    gemm_tf32<<<gproj, 256, GEMM_SMEM_BYTES>>>(y, Wp, Wp, Wp, out, out, out,
                                               nullptr, nullptr, T_LEN, DIM, DIM);
}

// round 3
// speedup vs baseline: 3.0113x; 2.1284x over previous
#include <cuda_runtime.h>
#include <math.h>

#define T_LEN 2048
#define DIM   768
#define NH    12
#define HD    64

// ---------------- scratch (no allocation allowed) ----------------
__device__ float g_q[T_LEN * DIM];
__device__ float g_k[T_LEN * DIM];
__device__ float g_v[T_LEN * DIM];
__device__ float g_y[T_LEN * DIM];

// ---------------- common tensor-core helpers ----------------
__device__ __forceinline__ unsigned f2tf32(float f) {
    unsigned u;
    asm("cvt.rna.tf32.f32 %0, %1;" : "=r"(u) : "f"(f));
    return u;
}

__device__ __forceinline__ void mma8(float* c, const unsigned* a, const unsigned* b) {
    asm volatile(
        "mma.sync.aligned.m16n8k8.row.col.f32.tf32.tf32.f32 "
        "{%0,%1,%2,%3}, {%4,%5,%6,%7}, {%8,%9}, {%0,%1,%2,%3};\n"
        : "+f"(c[0]), "+f"(c[1]), "+f"(c[2]), "+f"(c[3])
        : "r"(a[0]), "r"(a[1]), "r"(a[2]), "r"(a[3]), "r"(b[0]), "r"(b[1]));
}

__device__ __forceinline__ void cp16(void* smem_dst, const void* gsrc) {
    unsigned d = (unsigned)__cvta_generic_to_shared(smem_dst);
    asm volatile("cp.async.ca.shared.global [%0], [%1], 16;\n" :: "r"(d), "l"(gsrc));
}

// =====================================================================
// tf32 tensor-core GEMM:  C = A @ B^T   (A [M,K], B [N,K], C [M,N])
// =====================================================================
#define KC      32
#define GSTRIDE 36
#define STAGE_FLOATS (2 * 128 * GSTRIDE)
#define GEMM_SMEM_BYTES (2 * STAGE_FLOATS * 4)

__device__ __forceinline__ void load_stage(float* As, float* Bs,
                                           const float* A, const float* B,
                                           int bm, int bn, int k0, int K, int tid)
{
    const int row = tid >> 3;
    const int col = (tid & 7) * 4;
#pragma unroll
    for (int p = 0; p < 4; p++) {
        const int r = row + p * 32;
        cp16(&As[r * GSTRIDE + col], A + (size_t)(bm + r) * K + k0 + col);
        cp16(&Bs[r * GSTRIDE + col], B + (size_t)(bn + r) * K + k0 + col);
    }
}

__global__ __launch_bounds__(256)
void gemm_tf32(const float* __restrict__ A,
               const float* __restrict__ W0, const float* __restrict__ W1,
               const float* __restrict__ W2,
               float* __restrict__ C0, float* __restrict__ C1, float* __restrict__ C2,
               const float* __restrict__ addsrc, const float* __restrict__ lamb_ptr,
               int M, int N, int K)
{
    extern __shared__ float sm[];

    const int z = blockIdx.z;
    const float* B = (z == 0) ? W0 : (z == 1) ? W1 : W2;
    float*       C = (z == 0) ? C0 : (z == 1) ? C1 : C2;

    const int tid  = threadIdx.x;
    const int lane = tid & 31;
    const int warp = tid >> 5;
    const int wm   = warp >> 2;
    const int wn   = warp & 3;
    const int bm   = blockIdx.y * 128;
    const int bn   = blockIdx.x * 128;
    const int gr   = lane >> 2;
    const int tig  = lane & 3;

    float acc[4][4][4];
#pragma unroll
    for (int mi = 0; mi < 4; mi++)
#pragma unroll
        for (int ni = 0; ni < 4; ni++)
#pragma unroll
            for (int r = 0; r < 4; r++) acc[mi][ni][r] = 0.f;

    const int nt = K / KC;

    load_stage(sm, sm + 128 * GSTRIDE, A, B, bm, bn, 0, K, tid);
    asm volatile("cp.async.commit_group;\n");

    for (int t = 0; t < nt; t++) {
        if (t + 1 < nt) {
            float* dst = sm + ((t + 1) & 1) * STAGE_FLOATS;
            load_stage(dst, dst + 128 * GSTRIDE, A, B, bm, bn, (t + 1) * KC, K, tid);
            asm volatile("cp.async.commit_group;\n");
            asm volatile("cp.async.wait_group 1;\n");
        } else {
            asm volatile("cp.async.wait_group 0;\n");
        }
        __syncthreads();

        const float* As = sm + (t & 1) * STAGE_FLOATS;
        const float* Bs = As + 128 * GSTRIDE;

#pragma unroll
        for (int ks = 0; ks < 4; ks++) {
            const int kk = ks * 8;
            unsigned a[4][4], b[4][2];
#pragma unroll
            for (int mi = 0; mi < 4; mi++) {
                const int r = wm * 64 + mi * 16 + gr;
                const int c = kk + tig;
                a[mi][0] = f2tf32(As[r * GSTRIDE + c]);
                a[mi][1] = f2tf32(As[(r + 8) * GSTRIDE + c]);
                a[mi][2] = f2tf32(As[r * GSTRIDE + c + 4]);
                a[mi][3] = f2tf32(As[(r + 8) * GSTRIDE + c + 4]);
            }
#pragma unroll
            for (int ni = 0; ni < 4; ni++) {
                const int n = wn * 32 + ni * 8 + gr;
                b[ni][0] = f2tf32(Bs[n * GSTRIDE + kk + tig]);
                b[ni][1] = f2tf32(Bs[n * GSTRIDE + kk + 4 + tig]);
            }
#pragma unroll
            for (int mi = 0; mi < 4; mi++)
#pragma unroll
                for (int ni = 0; ni < 4; ni++)
                    mma8(acc[mi][ni], a[mi], b[ni]);
        }
        __syncthreads();
    }

    const bool blend = (z == 2) && (addsrc != nullptr);
    const float lb = blend ? *lamb_ptr : 0.f;
    const float om = 1.f - lb;

#pragma unroll
    for (int mi = 0; mi < 4; mi++) {
#pragma unroll
        for (int ni = 0; ni < 4; ni++) {
            const int r0 = bm + wm * 64 + mi * 16 + gr;
            const int c0 = bn + wn * 32 + ni * 8 + tig * 2;
            float2 v0 = make_float2(acc[mi][ni][0], acc[mi][ni][1]);
            float2 v1 = make_float2(acc[mi][ni][2], acc[mi][ni][3]);
            if (blend) {
                const float* s0 = addsrc + (size_t)r0 * N + c0;
                const float* s1 = addsrc + (size_t)(r0 + 8) * N + c0;
                v0.x = om * v0.x + lb * s0[0];
                v0.y = om * v0.y + lb * s0[1];
                v1.x = om * v1.x + lb * s1[0];
                v1.y = om * v1.y + lb * s1[1];
            }
            *(float2*)(C + (size_t)r0 * N + c0)       = v0;
            *(float2*)(C + (size_t)(r0 + 8) * N + c0) = v1;
        }
    }
}

// ---------------- RMSNorm + RoPE (in place on g_q / g_k) ----------------
__global__ __launch_bounds__(256)
void norm_rope_kernel()
{
    const int wid  = blockIdx.x * 8 + (threadIdx.x >> 5);
    const int lane = threadIdx.x & 31;
    const int tsel = wid / (T_LEN * NH);
    const int rem  = wid % (T_LEN * NH);
    const int t = rem / NH;
    const int h = rem % NH;

    float* base = (tsel ? g_k : g_q) + (size_t)t * DIM + h * HD;

    float x1 = base[lane];
    float x2 = base[lane + 32];

    float ss = x1 * x1 + x2 * x2;
#pragma unroll
    for (int o = 16; o; o >>= 1) ss += __shfl_xor_sync(0xffffffffu, ss, o);
    const float ms = ss * (1.f / 64.f);
    const float rn = rsqrtf(ms + 1.1920929e-07f);
    x1 *= rn; x2 *= rn;

    const float inv = expf(-(float)lane * 0.28782313662425572f); // ln(1e4)/32
    const float ang = (float)t * inv;
    const float c = cosf(ang);
    const float s = sinf(ang);

    base[lane]      =  x1 * c + x2 * s;
    base[lane + 32] = -x1 * s + x2 * c;
}

// =====================================================================
// tensor-core causal flash attention (tf32 MMA, fixed-shift softmax)
// CTA = (64-query block, head); 4 warps, warp owns 16 query rows.
// Scores bounded: |s| <= 8 exactly (unit-RMS q,k, scale 1/8) -> p=exp(s-8).
// =====================================================================
#define AKSTR 68       // K & P smem row stride (conflict-free for (gr,tig) reads)
#define AVSTR 72       // V smem row stride (conflict-free for (tig,gr) reads)
#define AT_K_OFF 0
#define AT_V_OFF (2 * 64 * AKSTR)
#define AT_P_OFF (AT_V_OFF + 2 * 64 * AVSTR)
#define ATTN_SMEM_FLOATS (AT_P_OFF + 64 * AKSTR)
#define ATTN_SMEM_BYTES  (ATTN_SMEM_FLOATS * 4)   // 89088

__global__ __launch_bounds__(128)
void attn_tc_kernel(const float* __restrict__ q, const float* __restrict__ k,
                    const float* __restrict__ v, float* __restrict__ y)
{
    extern __shared__ float sm[];
    float* k_s = sm + AT_K_OFF;     // [2][64][AKSTR]
    float* v_s = sm + AT_V_OFF;     // [2][64][AVSTR]
    float* p_s = sm + AT_P_OFF;     // [64][AKSTR] (tf32 bits)

    const int h   = blockIdx.x;
    const int qb  = (gridDim.y - 1) - blockIdx.y;   // longest-first
    const int q0  = qb * 64;
    const int tid = threadIdx.x;
    const int w    = tid >> 5;
    const int lane = tid & 31;
    const int gr   = lane >> 2;
    const int tig  = lane & 3;
    const int wrow = w * 16;

    // ---- Q fragments: load once, scale by 1/8, convert to tf32 ----
    unsigned aq[8][4];
    {
        const float* qb_ = q + (size_t)(q0 + wrow) * DIM + h * HD;
#pragma unroll
        for (int ks = 0; ks < 8; ks++) {
            const int c = ks * 8 + tig;
            aq[ks][0] = f2tf32(0.125f * qb_[(size_t)gr * DIM + c]);
            aq[ks][1] = f2tf32(0.125f * qb_[(size_t)(gr + 8) * DIM + c]);
            aq[ks][2] = f2tf32(0.125f * qb_[(size_t)gr * DIM + c + 4]);
            aq[ks][3] = f2tf32(0.125f * qb_[(size_t)(gr + 8) * DIM + c + 4]);
        }
    }

    float oacc[8][4];
#pragma unroll
    for (int ni = 0; ni < 8; ni++)
#pragma unroll
        for (int r = 0; r < 4; r++) oacc[ni][r] = 0.f;
    float l0 = 0.f, l1 = 0.f;

    // ---- cp.async KV stage loader ----
    const int ld_row = tid >> 1;
    const int ld_c0  = (tid & 1) * 32;
#define LOAD_KV(KB, STG) do {                                                  \
        const float* kg = k + (size_t)((KB) * 64 + ld_row) * DIM + h * HD + ld_c0; \
        const float* vg = v + (size_t)((KB) * 64 + ld_row) * DIM + h * HD + ld_c0; \
        float* kd = k_s + (STG) * 64 * AKSTR + ld_row * AKSTR + ld_c0;         \
        float* vd = v_s + (STG) * 64 * AVSTR + ld_row * AVSTR + ld_c0;         \
        _Pragma("unroll")                                                      \
        for (int i_ = 0; i_ < 8; i_++) {                                       \
            cp16(kd + i_ * 4, kg + i_ * 4);                                    \
            cp16(vd + i_ * 4, vg + i_ * 4);                                    \
        }                                                                      \
    } while (0)

    LOAD_KV(0, 0);
    asm volatile("cp.async.commit_group;\n");

    for (int kb = 0; kb <= qb; kb++) {
        if (kb < qb) {
            LOAD_KV(kb + 1, (kb + 1) & 1);
            asm volatile("cp.async.commit_group;\n");
            asm volatile("cp.async.wait_group 1;\n");
        } else {
            asm volatile("cp.async.wait_group 0;\n");
        }
        __syncthreads();

        const float* ks_ = k_s + (kb & 1) * 64 * AKSTR;
        const float* vs_ = v_s + (kb & 1) * 64 * AVSTR;

        // ---- S = Q K^T ----
        float s[8][4];
#pragma unroll
        for (int ni = 0; ni < 8; ni++)
#pragma unroll
            for (int r = 0; r < 4; r++) s[ni][r] = 0.f;

#pragma unroll
        for (int ni = 0; ni < 8; ni++) {
            const float* kr = ks_ + (ni * 8 + gr) * AKSTR + tig;
#pragma unroll
            for (int ks = 0; ks < 8; ks++) {
                unsigned b[2];
                b[0] = f2tf32(kr[ks * 8]);
                b[1] = f2tf32(kr[ks * 8 + 4]);
                mma8(s[ni], aq[ks], b);
            }
        }

        // ---- fixed-shift softmax, stage P as tf32 bits ----
        const bool diag = (kb == qb);
        const int r0 = wrow + gr, r1 = r0 + 8;
#pragma unroll
        for (int ni = 0; ni < 8; ni++) {
            const int c0 = ni * 8 + 2 * tig;
            float p0 = __expf(s[ni][0] - 8.f);
            float p1 = __expf(s[ni][1] - 8.f);
            float p2 = __expf(s[ni][2] - 8.f);
            float p3 = __expf(s[ni][3] - 8.f);
            if (diag) {
                if (c0 > r0)     p0 = 0.f;
                if (c0 + 1 > r0) p1 = 0.f;
                if (c0 > r1)     p2 = 0.f;
                if (c0 + 1 > r1) p3 = 0.f;
            }
            l0 += p0 + p1;
            l1 += p2 + p3;
            uint2 w0; w0.x = f2tf32(p0); w0.y = f2tf32(p1);
            uint2 w1; w1.x = f2tf32(p2); w1.y = f2tf32(p3);
            *(uint2*)&p_s[r0 * AKSTR + c0] = w0;
            *(uint2*)&p_s[r1 * AKSTR + c0] = w1;
        }
        __syncwarp();

        // ---- O += P V ----
        const unsigned* pu = (const unsigned*)p_s;
#pragma unroll
        for (int ks = 0; ks < 8; ks++) {
            unsigned ap[4];
            ap[0] = pu[r0 * AKSTR + ks * 8 + tig];
            ap[1] = pu[r1 * AKSTR + ks * 8 + tig];
            ap[2] = pu[r0 * AKSTR + ks * 8 + 4 + tig];
            ap[3] = pu[r1 * AKSTR + ks * 8 + 4 + tig];
            const float* vr = vs_ + (ks * 8 + tig) * AVSTR + gr;
#pragma unroll
            for (int ni = 0; ni < 8; ni++) {
                unsigned b[2];
                b[0] = f2tf32(vr[ni * 8]);
                b[1] = f2tf32(vr[4 * AVSTR + ni * 8]);
                mma8(oacc[ni], ap, b);
            }
        }
        __syncthreads();
    }

    // ---- finalize: reduce l over the 4-lane row group, normalize, store ----
    l0 += __shfl_xor_sync(0xffffffffu, l0, 1);
    l0 += __shfl_xor_sync(0xffffffffu, l0, 2);
    l1 += __shfl_xor_sync(0xffffffffu, l1, 1);
    l1 += __shfl_xor_sync(0xffffffffu, l1, 2);
    const float inv0 = 1.f / l0;
    const float inv1 = 1.f / l1;

    const int r0 = wrow + gr;
#pragma unroll
    for (int ni = 0; ni < 8; ni++) {
        const int c = ni * 8 + 2 * tig;
        float2 o0 = make_float2(oacc[ni][0] * inv0, oacc[ni][1] * inv0);
        float2 o1 = make_float2(oacc[ni][2] * inv1, oacc[ni][3] * inv1);
        *(float2*)&y[(size_t)(q0 + r0) * DIM + h * HD + c]     = o0;
        *(float2*)&y[(size_t)(q0 + r0 + 8) * DIM + h * HD + c] = o1;
    }
}

// ---------------- launch ----------------
extern "C" void kernel_launch(void* const* d_in, const int* in_sizes, int n_in,
                              void* d_out, int out_size)
{
    const float* x    = (const float*)d_in[0];
    const float* vi   = (const float*)d_in[1];
    const float* Wq   = (const float*)d_in[2];
    const float* Wk   = (const float*)d_in[3];
    const float* Wv   = (const float*)d_in[4];
    const float* Wp   = (const float*)d_in[5];
    const float* lamb = (const float*)d_in[6];
    float* out = (float*)d_out;

    float *q, *k, *v, *y;
    cudaGetSymbolAddress((void**)&q, g_q);
    cudaGetSymbolAddress((void**)&k, g_k);
    cudaGetSymbolAddress((void**)&v, g_v);
    cudaGetSymbolAddress((void**)&y, g_y);

    cudaFuncSetAttribute(gemm_tf32, cudaFuncAttributeMaxDynamicSharedMemorySize,
                         GEMM_SMEM_BYTES);
    cudaFuncSetAttribute(attn_tc_kernel, cudaFuncAttributeMaxDynamicSharedMemorySize,
                         ATTN_SMEM_BYTES);

    // fused QKV GEMM (z selects Wq/Wk/Wv; z==2 blends with vi)
    dim3 gqkv(DIM / 128, T_LEN / 128, 3);
    gemm_tf32<<<gqkv, 256, GEMM_SMEM_BYTES>>>(x, Wq, Wk, Wv, q, k, v, vi, lamb,
                                              T_LEN, DIM, DIM);

    // RMSNorm + RoPE on q and k (in place)
    norm_rope_kernel<<<(2 * T_LEN * NH) / 8, 256>>>();

    // tensor-core causal attention
    dim3 gattn(NH, T_LEN / 64);
    attn_tc_kernel<<<gattn, 128, ATTN_SMEM_BYTES>>>(q, k, v, y);

    // output projection
    dim3 gproj(DIM / 128, T_LEN / 128, 1);
    gemm_tf32<<<gproj, 256, GEMM_SMEM_BYTES>>>(y, Wp, Wp, Wp, out, out, out,
                                               nullptr, nullptr, T_LEN, DIM, DIM);
}